// round 3
// baseline (speedup 1.0000x reference)
#include <cuda_runtime.h>
#include <cstddef>

#define C_DIM 64
#define K_DIM 64
#define P_DIM (256 * 256)        // H*W = 65536
#define RED_BLOCKS 64            // reduction blocks (1024 pixels each)
#define PX_PER_RED (P_DIM / RED_BLOCKS)          // 1024
#define N4_PER_REP (C_DIM * P_DIM / 4)           // 1,048,576 float4 per replica
#define CHUNKS_PER_REP 1024
#define F4_PER_CHUNK (N4_PER_REP / CHUNKS_PER_REP)  // 1024 float4 = 16KB

// Per-block partial sums — written unconditionally, no zeroing needed.
__device__ float g_partial[RED_BLOCKS][K_DIM * C_DIM];   // 1 MB
__device__ float g_pcnt[RED_BLOCKS][K_DIM];              // 16 KB
__device__ unsigned int g_done;                          // zero-initialized; reset each launch

// ---------------------------------------------------------------------------
// Fused kernel:
//   blocks [0, 64)        : per-region partial sums (1024 pixels each)
//   block  64             : spin-wait for partials, compute means, reset flag
//   blocks [65, 65+65536) : 1 GiB broadcast copy (DRAM-write-bound)
// Blocks 0..64 are all wave-1 co-resident (65 < 148 SMs) -> spin is safe.
// ---------------------------------------------------------------------------
__global__ __launch_bounds__(256) void fused_kernel(
    const float* __restrict__ x, const float* __restrict__ oh,
    float4* __restrict__ out4, float* __restrict__ out_means)
{
    __shared__ float ssum[K_DIM][C_DIM + 1];  // padded rows vs bank conflicts
    __shared__ float scnt[K_DIM];

    int bid = blockIdx.x;
    int tid = threadIdx.x;

    if (bid < RED_BLOCKS) {
        // ---- reduction path ----
        for (int i = tid; i < K_DIM * (C_DIM + 1); i += 256)
            (&ssum[0][0])[i] = 0.0f;
        if (tid < K_DIM) scnt[tid] = 0.0f;
        __syncthreads();

        #pragma unroll
        for (int batch = 0; batch < PX_PER_RED / 256; batch++) {
            int p = bid * PX_PER_RED + batch * 256 + tid;

            // Recover the one-hot label (coalesced scan over K).
            int label = 0;
            #pragma unroll 8
            for (int k = 0; k < K_DIM; k++) {
                if (__ldg(&oh[(size_t)k * P_DIM + p]) != 0.0f) label = k;
            }
            atomicAdd(&scnt[label], 1.0f);

            #pragma unroll 8
            for (int c = 0; c < C_DIM; c++) {
                atomicAdd(&ssum[label][c], __ldg(&x[(size_t)c * P_DIM + p]));
            }
        }
        __syncthreads();

        // Non-atomic flush to this block's private partial slot.
        for (int i = tid; i < K_DIM * C_DIM; i += 256) {
            g_partial[bid][i] = ssum[i >> 6][i & 63];
        }
        if (tid < K_DIM) g_pcnt[bid][tid] = scnt[tid];

        // Signal completion (release).
        __syncthreads();
        __threadfence();
        if (tid == 0) atomicAdd(&g_done, 1u);

    } else if (bid == RED_BLOCKS) {
        // ---- means path: wait for all reduction partials ----
        if (tid == 0) {
            while (atomicAdd(&g_done, 0u) < RED_BLOCKS) __nanosleep(200);
        }
        __syncthreads();
        __threadfence();  // acquire

        // Denominators: threads 0..63, one k each.
        if (tid < K_DIM) {
            float cnt = 0.0f;
            #pragma unroll 8
            for (int r = 0; r < RED_BLOCKS; r++) cnt += g_pcnt[r][tid];
            scnt[tid] = cnt + (cnt == 0.0f ? 1.0f : 0.0f);
        }
        __syncthreads();

        // 4096 outputs, 256 threads -> 16 each; partials are L2-resident.
        for (int i = tid; i < K_DIM * C_DIM; i += 256) {
            float s = 0.0f;
            #pragma unroll 8
            for (int r = 0; r < RED_BLOCKS; r++) s += g_partial[r][i];
            out_means[i] = s / scnt[i >> 6];
        }

        // Reset for the next graph replay (all increments already observed).
        __syncthreads();
        if (tid == 0) atomicExch(&g_done, 0u);

    } else {
        // ---- broadcast path: one 16 KB chunk of one replica ----
        int b  = bid - (RED_BLOCKS + 1);
        int k  = b >> 10;                    // replica index
        int cb = b & (CHUNKS_PER_REP - 1);

        const float4* src = (const float4*)x + (size_t)cb * F4_PER_CHUNK;
        float4* dst = out4 + (size_t)k * N4_PER_REP + (size_t)cb * F4_PER_CHUNK;

        float4 v0 = __ldg(src + tid);
        float4 v1 = __ldg(src + 256 + tid);
        float4 v2 = __ldg(src + 512 + tid);
        float4 v3 = __ldg(src + 768 + tid);
        __stcs(dst + tid,       v0);
        __stcs(dst + 256 + tid, v1);
        __stcs(dst + 512 + tid, v2);
        __stcs(dst + 768 + tid, v3);
    }
}

// ---------------------------------------------------------------------------
extern "C" void kernel_launch(void* const* d_in, const int* in_sizes, int n_in,
                              void* d_out, int out_size)
{
    const float* x  = (const float*)d_in[0];   // [1, 64, 256, 256]
    const float* oh = (const float*)d_in[1];   // [1, 64, 256, 256] one-hot
    float* out = (float*)d_out;

    // Output layout: input_r (K*C*H*W floats) then regional_means (K*C).
    float* out_means = out + (size_t)out_size - (size_t)(K_DIM * C_DIM);

    fused_kernel<<<RED_BLOCKS + 1 + K_DIM * CHUNKS_PER_REP, 256>>>(
        x, oh, (float4*)out, out_means);
}

// round 4
// speedup vs baseline: 1.5633x; 1.5633x over previous
#include <cuda_runtime.h>
#include <cstddef>

#define C_DIM 64
#define K_DIM 64
#define P_DIM (256 * 256)        // H*W = 65536
#define RED_BLOCKS 256           // reduction blocks (256 pixels each)
#define N4_PER_REP (C_DIM * P_DIM / 4)   // 1,048,576 float4 per replica
#define CHUNKS_PER_REP 1024
#define F4_PER_CHUNK (N4_PER_REP / CHUNKS_PER_REP)  // 1024 float4 = 16KB

// Transposed partials: g_partial[i][r] so the means kernel reads contiguous r.
// Written unconditionally each launch -> no zeroing needed.
__device__ float g_partial[K_DIM * C_DIM][RED_BLOCKS];   // 4 MB
__device__ float g_pcnt[K_DIM][RED_BLOCKS];              // 64 KB

// ---------------------------------------------------------------------------
// Fused kernel (R2 structure, proven 142us): blocks [0,256) reduce, the rest
// stream the 1 GiB broadcast copy. Reduction hides under the DRAM-bound copy.
// ---------------------------------------------------------------------------
__global__ __launch_bounds__(256) void fused_kernel(
    const float* __restrict__ x, const float* __restrict__ oh,
    float4* __restrict__ out4)
{
    __shared__ float ssum[K_DIM][C_DIM + 1];  // padded rows vs bank conflicts
    __shared__ float scnt[K_DIM];

    int bid = blockIdx.x;
    int tid = threadIdx.x;

    if (bid < RED_BLOCKS) {
        // ---- reduction path: 256 pixels per block ----
        for (int i = tid; i < K_DIM * (C_DIM + 1); i += 256)
            (&ssum[0][0])[i] = 0.0f;
        if (tid < K_DIM) scnt[tid] = 0.0f;
        __syncthreads();

        int p = bid * 256 + tid;

        // Recover the one-hot label (coalesced scan over K).
        int label = 0;
        #pragma unroll 8
        for (int k = 0; k < K_DIM; k++) {
            if (__ldg(&oh[(size_t)k * P_DIM + p]) != 0.0f) label = k;
        }
        atomicAdd(&scnt[label], 1.0f);

        #pragma unroll 8
        for (int c = 0; c < C_DIM; c++) {
            atomicAdd(&ssum[label][c], __ldg(&x[(size_t)c * P_DIM + p]));
        }
        __syncthreads();

        // Flush to transposed partial slot (scattered 4B stores, hidden under copy).
        for (int i = tid; i < K_DIM * C_DIM; i += 256) {
            g_partial[i][bid] = ssum[i >> 6][i & 63];
        }
        if (tid < K_DIM) g_pcnt[tid][bid] = scnt[tid];
    } else {
        // ---- broadcast path: one 16 KB chunk of one replica ----
        int b  = bid - RED_BLOCKS;
        int k  = b >> 10;                    // replica index
        int cb = b & (CHUNKS_PER_REP - 1);

        const float4* src = (const float4*)x + (size_t)cb * F4_PER_CHUNK;
        float4* dst = out4 + (size_t)k * N4_PER_REP + (size_t)cb * F4_PER_CHUNK;

        float4 v0 = __ldg(src + tid);
        float4 v1 = __ldg(src + 256 + tid);
        float4 v2 = __ldg(src + 512 + tid);
        float4 v3 = __ldg(src + 768 + tid);
        __stcs(dst + tid,       v0);
        __stcs(dst + 256 + tid, v1);
        __stcs(dst + 512 + tid, v2);
        __stcs(dst + 768 + tid, v3);
    }
}

// ---------------------------------------------------------------------------
// Means: one warp per (k,c) output. Lanes read 2 contiguous float4 each
// (fully coalesced, L2-resident), butterfly-reduce sum and count.
// 512 blocks x 256 threads = 4096 warps.
// ---------------------------------------------------------------------------
__global__ __launch_bounds__(256) void means_kernel(float* __restrict__ out_means)
{
    int warp_g = (blockIdx.x * 256 + threadIdx.x) >> 5;   // 0..4095 = output index
    int lane   = threadIdx.x & 31;
    int k      = warp_g >> 6;

    const float4* prow = (const float4*)&g_partial[warp_g][0];  // 64 float4
    const float4* crow = (const float4*)&g_pcnt[k][0];          // 64 float4

    float4 a = __ldg(prow + lane);
    float4 b = __ldg(prow + 32 + lane);
    float4 ca = __ldg(crow + lane);
    float4 cb = __ldg(crow + 32 + lane);

    float s   = (a.x + a.y) + (a.z + a.w) + (b.x + b.y) + (b.z + b.w);
    float cnt = (ca.x + ca.y) + (ca.z + ca.w) + (cb.x + cb.y) + (cb.z + cb.w);

    #pragma unroll
    for (int off = 16; off > 0; off >>= 1) {
        s   += __shfl_xor_sync(0xFFFFFFFFu, s, off);
        cnt += __shfl_xor_sync(0xFFFFFFFFu, cnt, off);
    }

    if (lane == 0) {
        float denom = cnt + (cnt == 0.0f ? 1.0f : 0.0f);
        out_means[warp_g] = s / denom;
    }
}

// ---------------------------------------------------------------------------
extern "C" void kernel_launch(void* const* d_in, const int* in_sizes, int n_in,
                              void* d_out, int out_size)
{
    const float* x  = (const float*)d_in[0];   // [1, 64, 256, 256]
    const float* oh = (const float*)d_in[1];   // [1, 64, 256, 256] one-hot
    float* out = (float*)d_out;

    // Output layout: input_r (K*C*H*W floats) then regional_means (K*C).
    float* out_means = out + (size_t)out_size - (size_t)(K_DIM * C_DIM);

    fused_kernel<<<RED_BLOCKS + K_DIM * CHUNKS_PER_REP, 256>>>(
        x, oh, (float4*)out);
    means_kernel<<<512, 256>>>(out_means);
}